// round 3
// baseline (speedup 1.0000x reference)
#include <cuda_runtime.h>
#include <math_constants.h>

// Problem constants
#define B_      4
#define C_      3072
#define T_      4096
#define K_      24
#define TD_     128
#define TILE_T  2
#define NTHR    256
#define EPS_    1e-5f
#define SCALE_  0.08838834764831845f   // 128^-0.5

// Shared-memory pool layout (float offsets)
#define OFF_WBUF 0        // 16384 floats : staged 128x128 weight chunk
#define OFF_TOK  16384    //  6144 floats : tok rows [48][128]; later attn-out
#define OFF_QKV  22528    // 18432 floats : qkv rows [48][384]; later y [48][128]
#define OFF_XS   40960    //  6144 floats : x slice rows [48][128] (kept for residual)
#define OFF_S    47104    //  1152 floats : attention scores [48][24]
#define SMEM_FLOATS 48256 // 193,024 bytes

// 48-row x 128-col GEMM: out[row][d] = sum_c in[row][c] * wb[c][d] + bias
// Thread (d = tid&127, rh = tid>>7) computes 24 outputs:
//   rows = { tt*24 + rh*12 + kk : tt in 0..1, kk in 0..11 }, acc[kk*2+tt]
__device__ __forceinline__ void gemm48(const float* __restrict__ sm_in,
                                       const float* __restrict__ wb,
                                       int d, int rh, float bias, float* acc)
{
#pragma unroll
    for (int i = 0; i < 24; i++) acc[i] = bias;
    for (int c = 0; c < 128; c += 4) {
        const float w0 = wb[(c + 0) * 128 + d];
        const float w1 = wb[(c + 1) * 128 + d];
        const float w2 = wb[(c + 2) * 128 + d];
        const float w3 = wb[(c + 3) * 128 + d];
#pragma unroll
        for (int kk = 0; kk < 12; kk++) {
#pragma unroll
            for (int tt = 0; tt < 2; tt++) {
                const float4 xv = *(const float4*)(sm_in + (tt * 24 + rh * 12 + kk) * 128 + c);
                float a = acc[kk * 2 + tt];
                a = fmaf(xv.x, w0, a);
                a = fmaf(xv.y, w1, a);
                a = fmaf(xv.z, w2, a);
                a = fmaf(xv.w, w3, a);
                acc[kk * 2 + tt] = a;
            }
        }
    }
}

__global__ void __launch_bounds__(NTHR, 1)
wanjoint_kernel(const float* __restrict__ x,
                const float* __restrict__ W_tok,  const float* __restrict__ b_tok,
                const float* __restrict__ g_norm,
                const float* __restrict__ W_qkv,  const float* __restrict__ b_qkv,
                const float* __restrict__ W_proj, const float* __restrict__ b_proj,
                const float* __restrict__ W_from, const float* __restrict__ b_from,
                float* __restrict__ out)
{
    extern __shared__ float sm[];
    const int tid  = threadIdx.x;
    const int d    = tid & 127;
    const int rh   = tid >> 7;
    const int lane = tid & 31;
    const int wrp  = tid >> 5;
    const int t0   = blockIdx.x * TILE_T;
    const int b    = blockIdx.y;
    const float* xb = x + (size_t)b * C_ * T_;

    // ---- P0: stage x slice (rows = tt*24+k, cols = c) and W_tok ----
    for (int idx = tid; idx < K_ * 128; idx += NTHR) {
        const int k = idx >> 7, c = idx & 127;
        const float2 v = *(const float2*)(xb + (size_t)(k * 128 + c) * T_ + t0);
        sm[OFF_XS + k * 128 + c]        = v.x;
        sm[OFF_XS + (24 + k) * 128 + c] = v.y;
    }
    for (int idx = tid; idx < 4096; idx += NTHR)
        ((float4*)(sm + OFF_WBUF))[idx] = ((const float4*)W_tok)[idx];
    __syncthreads();

    float acc[24];

    // ---- P1: tok = x_slice @ W_tok + b_tok ----
    gemm48(sm + OFF_XS, sm + OFF_WBUF, d, rh, b_tok[d], acc);
#pragma unroll
    for (int kk = 0; kk < 12; kk++) {
        sm[OFF_TOK + (rh * 12 + kk) * 128 + d]        = acc[kk * 2 + 0];
        sm[OFF_TOK + (24 + rh * 12 + kk) * 128 + d]   = acc[kk * 2 + 1];
    }
    __syncthreads();

    // ---- P1.5: RMSNorm rows of tok (warp per row) ----
    {
        const float4 g4 = *(const float4*)(g_norm + lane * 4);
        for (int r = wrp; r < 48; r += 8) {
            float4 v = *(const float4*)(sm + OFF_TOK + r * 128 + lane * 4);
            float ss = v.x * v.x + v.y * v.y + v.z * v.z + v.w * v.w;
#pragma unroll
            for (int o = 16; o > 0; o >>= 1) ss += __shfl_xor_sync(0xffffffffu, ss, o);
            const float rms = rsqrtf(ss * (1.0f / 128.0f) + EPS_);
            v.x *= rms * g4.x; v.y *= rms * g4.y; v.z *= rms * g4.z; v.w *= rms * g4.w;
            *(float4*)(sm + OFF_TOK + r * 128 + lane * 4) = v;
        }
    }
    __syncthreads();

    // ---- P2: qkv = tok @ W_qkv + b_qkv, staged in 3 chunks of 128 cols ----
    for (int p = 0; p < 3; p++) {
        for (int idx = tid; idx < 4096; idx += NTHR) {
            const int c = idx >> 5, dd = (idx & 31) << 2;
            *(float4*)(sm + OFF_WBUF + c * 128 + dd) =
                *(const float4*)(W_qkv + c * 384 + p * 128 + dd);
        }
        __syncthreads();
        gemm48(sm + OFF_TOK, sm + OFF_WBUF, d, rh, b_qkv[p * 128 + d], acc);
#pragma unroll
        for (int kk = 0; kk < 12; kk++) {
            sm[OFF_QKV + (rh * 12 + kk) * 384 + p * 128 + d]      = acc[kk * 2 + 0];
            sm[OFF_QKV + (24 + rh * 12 + kk) * 384 + p * 128 + d] = acc[kk * 2 + 1];
        }
        __syncthreads();
    }

    // ---- P3a: scores s[tt][i][j] = SCALE * dot(q_i, k_j) ----
    for (int pp = tid; pp < 2 * 24 * 24; pp += NTHR) {
        const int tt = pp / 576;
        const int ij = pp % 576;
        const int i = ij / 24, j = ij % 24;
        const float4* qa = (const float4*)(sm + OFF_QKV + (tt * 24 + i) * 384);
        const float4* ka = (const float4*)(sm + OFF_QKV + (tt * 24 + j) * 384 + 128);
        float s = 0.f;
#pragma unroll
        for (int cc = 0; cc < 32; cc++) {
            const float4 a = qa[cc], bb = ka[cc];
            s += a.x * bb.x + a.y * bb.y + a.z * bb.z + a.w * bb.w;
        }
        sm[OFF_S + pp] = s * SCALE_;
    }
    __syncthreads();

    // ---- P3b: softmax per row (warp per row, 24 valid lanes) ----
    for (int r = wrp; r < 48; r += 8) {
        const float v = (lane < 24) ? sm[OFF_S + r * 24 + lane] : -CUDART_INF_F;
        float m = v;
#pragma unroll
        for (int o = 16; o > 0; o >>= 1) m = fmaxf(m, __shfl_xor_sync(0xffffffffu, m, o));
        const float e = (lane < 24) ? __expf(v - m) : 0.f;
        float ssum = e;
#pragma unroll
        for (int o = 16; o > 0; o >>= 1) ssum += __shfl_xor_sync(0xffffffffu, ssum, o);
        if (lane < 24) sm[OFF_S + r * 24 + lane] = e / ssum;
    }
    __syncthreads();

    // ---- P3c: o = P @ V  (written over tok region) ----
    {
#pragma unroll
        for (int i = 0; i < 24; i++) acc[i] = 0.f;
        for (int j = 0; j < 24; j++) {
            const float v0 = sm[OFF_QKV + j * 384 + 256 + d];
            const float v1 = sm[OFF_QKV + (24 + j) * 384 + 256 + d];
#pragma unroll
            for (int kk = 0; kk < 12; kk++) {
                acc[kk * 2 + 0] = fmaf(sm[OFF_S + (rh * 12 + kk) * 24 + j],      v0, acc[kk * 2 + 0]);
                acc[kk * 2 + 1] = fmaf(sm[OFF_S + (24 + rh * 12 + kk) * 24 + j], v1, acc[kk * 2 + 1]);
            }
        }
#pragma unroll
        for (int kk = 0; kk < 12; kk++) {
            sm[OFF_TOK + (rh * 12 + kk) * 128 + d]      = acc[kk * 2 + 0];
            sm[OFF_TOK + (24 + rh * 12 + kk) * 128 + d] = acc[kk * 2 + 1];
        }
    }
    __syncthreads();

    // ---- P4: y = o @ W_proj + b_proj  (y over qkv region, stride 128) ----
    for (int idx = tid; idx < 4096; idx += NTHR)
        ((float4*)(sm + OFF_WBUF))[idx] = ((const float4*)W_proj)[idx];
    __syncthreads();
    gemm48(sm + OFF_TOK, sm + OFF_WBUF, d, rh, b_proj[d], acc);
#pragma unroll
    for (int kk = 0; kk < 12; kk++) {
        sm[OFF_QKV + (rh * 12 + kk) * 128 + d]      = acc[kk * 2 + 0];
        sm[OFF_QKV + (24 + rh * 12 + kk) * 128 + d] = acc[kk * 2 + 1];
    }
    __syncthreads();

    // ---- P5: r = y @ W_from + b_from ; out = x + r ----
    for (int idx = tid; idx < 4096; idx += NTHR)
        ((float4*)(sm + OFF_WBUF))[idx] = ((const float4*)W_from)[idx];
    __syncthreads();
    gemm48(sm + OFF_QKV, sm + OFF_WBUF, d, rh, b_from[d], acc);

    float* ob = out + (size_t)b * C_ * T_;
#pragma unroll
    for (int kk = 0; kk < 12; kk++) {
        const int k = rh * 12 + kk;
        float2 r2;
        r2.x = acc[kk * 2 + 0] + sm[OFF_XS + k * 128 + d];
        r2.y = acc[kk * 2 + 1] + sm[OFF_XS + (24 + k) * 128 + d];
        *(float2*)(ob + (size_t)(k * 128 + d) * T_ + t0) = r2;
    }
}

extern "C" void kernel_launch(void* const* d_in, const int* in_sizes, int n_in,
                              void* d_out, int out_size)
{
    (void)in_sizes; (void)n_in; (void)out_size;
    const float* x      = (const float*)d_in[0];
    const float* W_tok  = (const float*)d_in[1];
    const float* b_tok  = (const float*)d_in[2];
    const float* g_norm = (const float*)d_in[3];
    const float* W_qkv  = (const float*)d_in[4];
    const float* b_qkv  = (const float*)d_in[5];
    const float* W_proj = (const float*)d_in[6];
    const float* b_proj = (const float*)d_in[7];
    const float* W_from = (const float*)d_in[8];
    const float* b_from = (const float*)d_in[9];
    float* out = (float*)d_out;

    cudaFuncSetAttribute(wanjoint_kernel,
                         cudaFuncAttributeMaxDynamicSharedMemorySize,
                         SMEM_FLOATS * sizeof(float));

    dim3 grid(T_ / TILE_T, B_);
    wanjoint_kernel<<<grid, NTHR, SMEM_FLOATS * sizeof(float)>>>(
        x, W_tok, b_tok, g_norm, W_qkv, b_qkv, W_proj, b_proj, W_from, b_from, out);
}

// round 4
// speedup vs baseline: 1.0008x; 1.0008x over previous
#include <cuda_runtime.h>
#include <math_constants.h>

// Problem constants
#define B_      4
#define C_      3072
#define T_      4096
#define K_      24
#define TD_     128
#define TILE_T  2
#define NTHR    256
#define EPS_    1e-5f
#define SCALE_  0.08838834764831845f   // 128^-0.5

// Shared-memory pool layout (float offsets)
#define OFF_WBUF 0        // 16384 floats : staged 128x128 weight chunk
#define OFF_TOK  16384    //  6144 floats : tok rows [48][128]; later attn-out
#define OFF_QKV  22528    // 18432 floats : qkv rows [48][384]; later y [48][128]
#define OFF_XS   40960    //  6144 floats : x slice rows [48][128] (kept for residual)
#define OFF_S    47104    //  1152 floats : attention scores [48][24]
#define SMEM_FLOATS 48256 // 193,024 bytes

// 48-row x 128-col GEMM: out[row][d] = sum_c in[row][c] * wb[c][d] + bias
// Thread (d = tid&127, rh = tid>>7) computes 24 outputs:
//   rows = { tt*24 + rh*12 + kk : tt in 0..1, kk in 0..11 }, acc[kk*2+tt]
__device__ __forceinline__ void gemm48(const float* __restrict__ sm_in,
                                       const float* __restrict__ wb,
                                       int d, int rh, float bias, float* acc)
{
#pragma unroll
    for (int i = 0; i < 24; i++) acc[i] = bias;
    for (int c = 0; c < 128; c += 4) {
        const float w0 = wb[(c + 0) * 128 + d];
        const float w1 = wb[(c + 1) * 128 + d];
        const float w2 = wb[(c + 2) * 128 + d];
        const float w3 = wb[(c + 3) * 128 + d];
#pragma unroll
        for (int kk = 0; kk < 12; kk++) {
#pragma unroll
            for (int tt = 0; tt < 2; tt++) {
                const float4 xv = *(const float4*)(sm_in + (tt * 24 + rh * 12 + kk) * 128 + c);
                float a = acc[kk * 2 + tt];
                a = fmaf(xv.x, w0, a);
                a = fmaf(xv.y, w1, a);
                a = fmaf(xv.z, w2, a);
                a = fmaf(xv.w, w3, a);
                acc[kk * 2 + tt] = a;
            }
        }
    }
}

__global__ void __launch_bounds__(NTHR, 1)
wanjoint_kernel(const float* __restrict__ x,
                const float* __restrict__ W_tok,  const float* __restrict__ b_tok,
                const float* __restrict__ g_norm,
                const float* __restrict__ W_qkv,  const float* __restrict__ b_qkv,
                const float* __restrict__ W_proj, const float* __restrict__ b_proj,
                const float* __restrict__ W_from, const float* __restrict__ b_from,
                float* __restrict__ out)
{
    extern __shared__ float sm[];
    const int tid  = threadIdx.x;
    const int d    = tid & 127;
    const int rh   = tid >> 7;
    const int lane = tid & 31;
    const int wrp  = tid >> 5;
    const int t0   = blockIdx.x * TILE_T;
    const int b    = blockIdx.y;
    const float* xb = x + (size_t)b * C_ * T_;

    // ---- P0: stage x slice (rows = tt*24+k, cols = c) and W_tok ----
    for (int idx = tid; idx < K_ * 128; idx += NTHR) {
        const int k = idx >> 7, c = idx & 127;
        const float2 v = *(const float2*)(xb + (size_t)(k * 128 + c) * T_ + t0);
        sm[OFF_XS + k * 128 + c]        = v.x;
        sm[OFF_XS + (24 + k) * 128 + c] = v.y;
    }
    for (int idx = tid; idx < 4096; idx += NTHR)
        ((float4*)(sm + OFF_WBUF))[idx] = ((const float4*)W_tok)[idx];
    __syncthreads();

    float acc[24];

    // ---- P1: tok = x_slice @ W_tok + b_tok ----
    gemm48(sm + OFF_XS, sm + OFF_WBUF, d, rh, b_tok[d], acc);
#pragma unroll
    for (int kk = 0; kk < 12; kk++) {
        sm[OFF_TOK + (rh * 12 + kk) * 128 + d]        = acc[kk * 2 + 0];
        sm[OFF_TOK + (24 + rh * 12 + kk) * 128 + d]   = acc[kk * 2 + 1];
    }
    __syncthreads();

    // ---- P1.5: RMSNorm rows of tok (warp per row) ----
    {
        const float4 g4 = *(const float4*)(g_norm + lane * 4);
        for (int r = wrp; r < 48; r += 8) {
            float4 v = *(const float4*)(sm + OFF_TOK + r * 128 + lane * 4);
            float ss = v.x * v.x + v.y * v.y + v.z * v.z + v.w * v.w;
#pragma unroll
            for (int o = 16; o > 0; o >>= 1) ss += __shfl_xor_sync(0xffffffffu, ss, o);
            const float rms = rsqrtf(ss * (1.0f / 128.0f) + EPS_);
            v.x *= rms * g4.x; v.y *= rms * g4.y; v.z *= rms * g4.z; v.w *= rms * g4.w;
            *(float4*)(sm + OFF_TOK + r * 128 + lane * 4) = v;
        }
    }
    __syncthreads();

    // ---- P2: qkv = tok @ W_qkv + b_qkv, staged in 3 chunks of 128 cols ----
    for (int p = 0; p < 3; p++) {
        for (int idx = tid; idx < 4096; idx += NTHR) {
            const int c = idx >> 5, dd = (idx & 31) << 2;
            *(float4*)(sm + OFF_WBUF + c * 128 + dd) =
                *(const float4*)(W_qkv + c * 384 + p * 128 + dd);
        }
        __syncthreads();
        gemm48(sm + OFF_TOK, sm + OFF_WBUF, d, rh, b_qkv[p * 128 + d], acc);
#pragma unroll
        for (int kk = 0; kk < 12; kk++) {
            sm[OFF_QKV + (rh * 12 + kk) * 384 + p * 128 + d]      = acc[kk * 2 + 0];
            sm[OFF_QKV + (24 + rh * 12 + kk) * 384 + p * 128 + d] = acc[kk * 2 + 1];
        }
        __syncthreads();
    }

    // ---- P3a: scores s[tt][i][j] = SCALE * dot(q_i, k_j) ----
    for (int pp = tid; pp < 2 * 24 * 24; pp += NTHR) {
        const int tt = pp / 576;
        const int ij = pp % 576;
        const int i = ij / 24, j = ij % 24;
        const float4* qa = (const float4*)(sm + OFF_QKV + (tt * 24 + i) * 384);
        const float4* ka = (const float4*)(sm + OFF_QKV + (tt * 24 + j) * 384 + 128);
        float s = 0.f;
#pragma unroll
        for (int cc = 0; cc < 32; cc++) {
            const float4 a = qa[cc], bb = ka[cc];
            s += a.x * bb.x + a.y * bb.y + a.z * bb.z + a.w * bb.w;
        }
        sm[OFF_S + pp] = s * SCALE_;
    }
    __syncthreads();

    // ---- P3b: softmax per row (warp per row, 24 valid lanes) ----
    for (int r = wrp; r < 48; r += 8) {
        const float v = (lane < 24) ? sm[OFF_S + r * 24 + lane] : -CUDART_INF_F;
        float m = v;
#pragma unroll
        for (int o = 16; o > 0; o >>= 1) m = fmaxf(m, __shfl_xor_sync(0xffffffffu, m, o));
        const float e = (lane < 24) ? __expf(v - m) : 0.f;
        float ssum = e;
#pragma unroll
        for (int o = 16; o > 0; o >>= 1) ssum += __shfl_xor_sync(0xffffffffu, ssum, o);
        if (lane < 24) sm[OFF_S + r * 24 + lane] = e / ssum;
    }
    __syncthreads();

    // ---- P3c: o = P @ V  (written over tok region) ----
    {
#pragma unroll
        for (int i = 0; i < 24; i++) acc[i] = 0.f;
        for (int j = 0; j < 24; j++) {
            const float v0 = sm[OFF_QKV + j * 384 + 256 + d];
            const float v1 = sm[OFF_QKV + (24 + j) * 384 + 256 + d];
#pragma unroll
            for (int kk = 0; kk < 12; kk++) {
                acc[kk * 2 + 0] = fmaf(sm[OFF_S + (rh * 12 + kk) * 24 + j],      v0, acc[kk * 2 + 0]);
                acc[kk * 2 + 1] = fmaf(sm[OFF_S + (24 + rh * 12 + kk) * 24 + j], v1, acc[kk * 2 + 1]);
            }
        }
#pragma unroll
        for (int kk = 0; kk < 12; kk++) {
            sm[OFF_TOK + (rh * 12 + kk) * 128 + d]      = acc[kk * 2 + 0];
            sm[OFF_TOK + (24 + rh * 12 + kk) * 128 + d] = acc[kk * 2 + 1];
        }
    }
    __syncthreads();

    // ---- P4: y = o @ W_proj + b_proj  (y over qkv region, stride 128) ----
    for (int idx = tid; idx < 4096; idx += NTHR)
        ((float4*)(sm + OFF_WBUF))[idx] = ((const float4*)W_proj)[idx];
    __syncthreads();
    gemm48(sm + OFF_TOK, sm + OFF_WBUF, d, rh, b_proj[d], acc);
#pragma unroll
    for (int kk = 0; kk < 12; kk++) {
        sm[OFF_QKV + (rh * 12 + kk) * 128 + d]      = acc[kk * 2 + 0];
        sm[OFF_QKV + (24 + rh * 12 + kk) * 128 + d] = acc[kk * 2 + 1];
    }
    __syncthreads();

    // ---- P5: r = y @ W_from + b_from ; out = x + r ----
    for (int idx = tid; idx < 4096; idx += NTHR)
        ((float4*)(sm + OFF_WBUF))[idx] = ((const float4*)W_from)[idx];
    __syncthreads();
    gemm48(sm + OFF_QKV, sm + OFF_WBUF, d, rh, b_from[d], acc);

    float* ob = out + (size_t)b * C_ * T_;
#pragma unroll
    for (int kk = 0; kk < 12; kk++) {
        const int k = rh * 12 + kk;
        float2 r2;
        r2.x = acc[kk * 2 + 0] + sm[OFF_XS + k * 128 + d];
        r2.y = acc[kk * 2 + 1] + sm[OFF_XS + (24 + k) * 128 + d];
        *(float2*)(ob + (size_t)(k * 128 + d) * T_ + t0) = r2;
    }
}

extern "C" void kernel_launch(void* const* d_in, const int* in_sizes, int n_in,
                              void* d_out, int out_size)
{
    (void)in_sizes; (void)n_in; (void)out_size;
    const float* x      = (const float*)d_in[0];
    const float* W_tok  = (const float*)d_in[1];
    const float* b_tok  = (const float*)d_in[2];
    const float* g_norm = (const float*)d_in[3];
    const float* W_qkv  = (const float*)d_in[4];
    const float* b_qkv  = (const float*)d_in[5];
    const float* W_proj = (const float*)d_in[6];
    const float* b_proj = (const float*)d_in[7];
    const float* W_from = (const float*)d_in[8];
    const float* b_from = (const float*)d_in[9];
    float* out = (float*)d_out;

    cudaFuncSetAttribute(wanjoint_kernel,
                         cudaFuncAttributeMaxDynamicSharedMemorySize,
                         SMEM_FLOATS * sizeof(float));

    dim3 grid(T_ / TILE_T, B_);
    wanjoint_kernel<<<grid, NTHR, SMEM_FLOATS * sizeof(float)>>>(
        x, W_tok, b_tok, g_norm, W_qkv, b_qkv, W_proj, b_proj, W_from, b_from, out);
}